// round 15
// baseline (speedup 1.0000x reference)
#include <cuda_runtime.h>
#include <cstdint>
#include <math.h>

// Problem constants
#define B_SZ   16
#define T_SZ   1024
#define C_SZ   256
#define H_SZ   8
#define D_SZ   32
#define M_ROWS (B_SZ * T_SZ)      // 16384
#define FF_SZ  (4 * C_SZ)         // 1024

// Scratch (allocation-free rule: __device__ globals)
__device__ float g_h  [M_ROWS * C_SZ];
__device__ float g_q  [M_ROWS * C_SZ];   // [B,H,T,D]  (pre-scaled log2e/16, tf32-rounded)
__device__ float g_k  [M_ROWS * C_SZ];   // tf32-rounded
__device__ float g_v  [M_ROWS * C_SZ];   // tf32-rounded
__device__ float g_att[M_ROWS * C_SZ];   // [B,T,C]  tf32-rounded
__device__ float g_x1 [M_ROWS * C_SZ];   // full fp32 (residual path)
__device__ float g_h2 [M_ROWS * C_SZ];   // tf32-rounded
__device__ float g_f1 [M_ROWS * FF_SZ];  // tf32-rounded
// Transposed (K-major) weights, tf32-rounded
__device__ float g_wqkvT[768 * 256];
__device__ float g_wprojT[256 * 256];
__device__ float g_w1T  [1024 * 256];
__device__ float g_w2T  [256 * 1024];

// ---------------------------------------------------------------------------
// mma.sync tf32 helpers
// ---------------------------------------------------------------------------
__device__ __forceinline__ uint32_t f2tf32(float x) {
    uint32_t r;
    asm("cvt.rna.tf32.f32 %0, %1;" : "=r"(r) : "f"(x));
    return r;
}
__device__ __forceinline__ float tf32f(float x) {
    return __uint_as_float(f2tf32(x));
}
__device__ __forceinline__ float ex2f(float x) {
    float r;
    asm("ex2.approx.f32 %0, %1;" : "=f"(r) : "f"(x));
    return r;
}
__device__ __forceinline__ void mma_tf32(float* d, const uint32_t* a, const uint32_t* b) {
    asm volatile(
        "mma.sync.aligned.m16n8k8.row.col.f32.tf32.tf32.f32 "
        "{%0,%1,%2,%3}, {%4,%5,%6,%7}, {%8,%9}, {%0,%1,%2,%3};\n"
        : "+f"(d[0]), "+f"(d[1]), "+f"(d[2]), "+f"(d[3])
        : "r"(a[0]), "r"(a[1]), "r"(a[2]), "r"(a[3]), "r"(b[0]), "r"(b[1]));
}

#define CP_ASYNC16(dst, src) \
    asm volatile("cp.async.ca.shared.global [%0], [%1], 16;" :: "r"(dst), "l"(src))
#define CP_COMMIT() asm volatile("cp.async.commit_group;" ::: "memory")
#define CP_WAIT1()  asm volatile("cp.async.wait_group 1;" ::: "memory")
#define CP_WAIT0()  asm volatile("cp.async.wait_group 0;" ::: "memory")

__device__ __forceinline__ uint32_t smem_u32(const void* p) {
    uint32_t a;
    asm("{ .reg .u64 t; cvta.to.shared.u64 t, %1; cvt.u32.u64 %0, t; }" : "=r"(a) : "l"(p));
    return a;
}

// ---------------------------------------------------------------------------
// Fused prep: blocks [0,768) = weight transposes/pack; [768, 768+2048) = LN1.
// ---------------------------------------------------------------------------
__global__ void prep_and_ln1(const float* __restrict__ wq, const float* __restrict__ wk,
                             const float* __restrict__ wv, const float* __restrict__ w_proj,
                             const float* __restrict__ w1, const float* __restrict__ w2,
                             float* __restrict__ wqkvT, float* __restrict__ wprojT,
                             float* __restrict__ w1T, float* __restrict__ w2T,
                             const float* __restrict__ x, const float* __restrict__ ln_g,
                             const float* __restrict__ ln_b, float* __restrict__ hout) {
    __shared__ float tile[32][33];
    int t = blockIdx.x;
    if (t < 768) {
        int tx = threadIdx.x & 31, ty = threadIdx.x >> 5;   // (32, 8)
        const float* in; float* out; int rows, cols, bx, by;
        if (t < 192) {
            int sel = t / 64, rem = t % 64;
            int h = rem >> 3, cbi = rem & 7;
            const float* w = (sel == 0) ? wq : (sel == 1) ? wk : wv;
            in  = w + h * (C_SZ * D_SZ);
            out = wqkvT + (size_t)(sel * 256 + h * 32) * C_SZ;
            rows = 256; cols = 32; by = cbi * 32; bx = 0;
        } else if (t < 256) {
            int r = t - 192; in = w_proj; out = wprojT; rows = 256; cols = 256;
            bx = (r & 7) * 32; by = (r >> 3) * 32;
        } else if (t < 512) {
            int r = t - 256; in = w1; out = w1T; rows = 256; cols = 1024;
            bx = (r & 31) * 32; by = (r >> 5) * 32;
        } else {
            int r = t - 512; in = w2; out = w2T; rows = 1024; cols = 256;
            bx = (r & 7) * 32; by = (r >> 3) * 32;
        }
        #pragma unroll
        for (int e = 0; e < 4; e++)
            tile[ty + e*8][tx] = in[(size_t)(by + ty + e*8) * cols + bx + tx];
        __syncthreads();
        #pragma unroll
        for (int e = 0; e < 4; e++)
            out[(size_t)(bx + ty + e*8) * rows + by + tx] = tf32f(tile[tx][ty + e*8]);
    } else {
        int warp = threadIdx.x >> 5;
        int lane = threadIdx.x & 31;
        int row  = (t - 768) * 8 + warp;

        const float4* xr = (const float4*)(x + (size_t)row * C_SZ);
        float4 v0 = xr[lane];
        float4 v1 = xr[lane + 32];

        float s  = v0.x + v0.y + v0.z + v0.w + v1.x + v1.y + v1.z + v1.w;
        float ss = v0.x*v0.x + v0.y*v0.y + v0.z*v0.z + v0.w*v0.w
                 + v1.x*v1.x + v1.y*v1.y + v1.z*v1.z + v1.w*v1.w;

        #pragma unroll
        for (int o = 16; o; o >>= 1) {
            s  += __shfl_xor_sync(0xFFFFFFFFu, s,  o);
            ss += __shfl_xor_sync(0xFFFFFFFFu, ss, o);
        }
        float mu  = s * (1.0f / C_SZ);
        float var = ss * (1.0f / C_SZ) - mu * mu;
        float inv = rsqrtf(var + 1e-5f);

        const float4* gr = (const float4*)ln_g;
        const float4* br = (const float4*)ln_b;
        float4 g0 = gr[lane], g1 = gr[lane + 32];
        float4 b0 = br[lane], b1 = br[lane + 32];

        float4 o0, o1;
        o0.x = tf32f((v0.x - mu) * inv * g0.x + b0.x);
        o0.y = tf32f((v0.y - mu) * inv * g0.y + b0.y);
        o0.z = tf32f((v0.z - mu) * inv * g0.z + b0.z);
        o0.w = tf32f((v0.w - mu) * inv * g0.w + b0.w);
        o1.x = tf32f((v1.x - mu) * inv * g1.x + b1.x);
        o1.y = tf32f((v1.y - mu) * inv * g1.y + b1.y);
        o1.z = tf32f((v1.z - mu) * inv * g1.z + b1.z);
        o1.w = tf32f((v1.w - mu) * inv * g1.w + b1.w);

        float4* orow = (float4*)(hout + (size_t)row * C_SZ);
        orow[lane]      = o0;
        orow[lane + 32] = o1;
    }
}

// ---------------------------------------------------------------------------
// LayerNorm (standalone, used for LN2)
// ---------------------------------------------------------------------------
__global__ void ln_kernel(const float* __restrict__ x,
                          const float* __restrict__ g,
                          const float* __restrict__ b,
                          float* __restrict__ out) {
    int warp = threadIdx.x >> 5;
    int lane = threadIdx.x & 31;
    int row  = blockIdx.x * 8 + warp;

    const float4* xr = (const float4*)(x + (size_t)row * C_SZ);
    float4 v0 = xr[lane];
    float4 v1 = xr[lane + 32];

    float s  = v0.x + v0.y + v0.z + v0.w + v1.x + v1.y + v1.z + v1.w;
    float ss = v0.x*v0.x + v0.y*v0.y + v0.z*v0.z + v0.w*v0.w
             + v1.x*v1.x + v1.y*v1.y + v1.z*v1.z + v1.w*v1.w;

    #pragma unroll
    for (int o = 16; o; o >>= 1) {
        s  += __shfl_xor_sync(0xFFFFFFFFu, s,  o);
        ss += __shfl_xor_sync(0xFFFFFFFFu, ss, o);
    }
    float mu  = s * (1.0f / C_SZ);
    float var = ss * (1.0f / C_SZ) - mu * mu;
    float inv = rsqrtf(var + 1e-5f);

    const float4* gr = (const float4*)g;
    const float4* br = (const float4*)b;
    float4 g0 = gr[lane], g1 = gr[lane + 32];
    float4 b0 = br[lane], b1 = br[lane + 32];

    float4 o0, o1;
    o0.x = tf32f((v0.x - mu) * inv * g0.x + b0.x);
    o0.y = tf32f((v0.y - mu) * inv * g0.y + b0.y);
    o0.z = tf32f((v0.z - mu) * inv * g0.z + b0.z);
    o0.w = tf32f((v0.w - mu) * inv * g0.w + b0.w);
    o1.x = tf32f((v1.x - mu) * inv * g1.x + b1.x);
    o1.y = tf32f((v1.y - mu) * inv * g1.y + b1.y);
    o1.z = tf32f((v1.z - mu) * inv * g1.z + b1.z);
    o1.w = tf32f((v1.w - mu) * inv * g1.w + b1.w);

    float4* orow = (float4*)(out + (size_t)row * C_SZ);
    orow[lane]      = o0;
    orow[lane + 32] = o1;
}

// ---------------------------------------------------------------------------
// tf32 HMMA GEMM, BM=128 BN=128 BK=32, 2-stage cp.async, 2 blocks/SM.
// Used for QKV (MODE 0) and FF1 (MODE 2) — grids large enough to fill chip.
// ---------------------------------------------------------------------------
#define PAD2 36
#define G2_TILE_W (128 * PAD2)                      // 4608 words per operand tile
#define GEMM_SMEM (2 * G2_TILE_W * 2 * 4)           // 73728 bytes
#define Q_SCALE 0.09016844f                         // (1/16) * log2(e)

template <int MODE>
__global__ __launch_bounds__(256, 2)
void gemm_tc(const float* __restrict__ A, const float* __restrict__ Bw,
             const float* __restrict__ bias, const float* __restrict__ res,
             float* __restrict__ out, float* __restrict__ out2, float* __restrict__ out3,
             int Ntot, int K) {
    extern __shared__ __align__(16) uint32_t dynsm[];

    const int tid  = threadIdx.x;
    const int wid  = tid >> 5;
    const int lane = tid & 31;
    const int g    = lane >> 2;
    const int tg   = lane & 3;
    const int wm   = wid & 1;
    const int wn   = wid >> 1;
    const int m0   = blockIdx.y * 128;
    const int n0   = blockIdx.x * 128;

    const int ld_row = tid >> 3;
    const int ld_c4  = (tid & 7) << 2;
    const uint32_t sbase = smem_u32(dynsm);

    float acc[4][4][4];
    #pragma unroll
    for (int i = 0; i < 4; i++)
        #pragma unroll
        for (int j = 0; j < 4; j++)
            #pragma unroll
            for (int r = 0; r < 4; r++) acc[i][j][r] = 0.0f;

    const int nchunks = K >> 5;

    {
        #pragma unroll
        for (int e = 0; e < 4; e++) {
            int row = ld_row + e * 32;
            CP_ASYNC16(sbase + (row * PAD2 + ld_c4) * 4,
                       A + (size_t)(m0 + row) * K + ld_c4);
            CP_ASYNC16(sbase + (2 * G2_TILE_W + row * PAD2 + ld_c4) * 4,
                       Bw + (size_t)(n0 + row) * K + ld_c4);
        }
        CP_COMMIT();
    }

    for (int c = 0; c < nchunks; c++) {
        CP_WAIT0();
        __syncthreads();
        if (c + 1 < nchunks) {
            const int st2 = (c + 1) & 1;
            const int k0 = (c + 1) << 5;
            #pragma unroll
            for (int e = 0; e < 4; e++) {
                int row = ld_row + e * 32;
                CP_ASYNC16(sbase + (st2 * G2_TILE_W + row * PAD2 + ld_c4) * 4,
                           A + (size_t)(m0 + row) * K + k0 + ld_c4);
                CP_ASYNC16(sbase + ((2 + st2) * G2_TILE_W + row * PAD2 + ld_c4) * 4,
                           Bw + (size_t)(n0 + row) * K + k0 + ld_c4);
            }
            CP_COMMIT();
        }
        const int st = c & 1;
        const uint32_t* As = dynsm + st * G2_TILE_W;
        const uint32_t* Bs = dynsm + (2 + st) * G2_TILE_W;

        #pragma unroll
        for (int kk = 0; kk < 32; kk += 8) {
            uint32_t af[4][4], bf[4][2];
            #pragma unroll
            for (int i = 0; i < 4; i++) {
                int r0 = wm * 64 + i * 16 + g;
                af[i][0] = As[r0 * PAD2 + kk + tg];
                af[i][1] = As[(r0 + 8) * PAD2 + kk + tg];
                af[i][2] = As[r0 * PAD2 + kk + tg + 4];
                af[i][3] = As[(r0 + 8) * PAD2 + kk + tg + 4];
            }
            #pragma unroll
            for (int j = 0; j < 4; j++) {
                int n = wn * 32 + j * 8 + g;
                bf[j][0] = Bs[n * PAD2 + kk + tg];
                bf[j][1] = Bs[n * PAD2 + kk + tg + 4];
            }
            #pragma unroll
            for (int i = 0; i < 4; i++)
                #pragma unroll
                for (int j = 0; j < 4; j++)
                    mma_tf32(acc[i][j], af[i], bf[j]);
        }
    }

    #pragma unroll
    for (int i = 0; i < 4; i++) {
        #pragma unroll
        for (int half = 0; half < 2; half++) {
            int m  = m0 + wm * 64 + i * 16 + g + half * 8;
            int bb = m >> 10, t = m & 1023;
            #pragma unroll
            for (int j = 0; j < 4; j++) {
                int col = n0 + wn * 32 + j * 8 + tg * 2;
                float2 vv = make_float2(acc[i][j][half * 2], acc[i][j][half * 2 + 1]);
                if (MODE == 0) {
                    int tsel = col >> 8;
                    int c2 = col & 255;
                    int hh = c2 >> 5, d = c2 & 31;
                    float* dst = (tsel == 0) ? out : (tsel == 1) ? out2 : out3;
                    if (tsel == 0) { vv.x *= Q_SCALE; vv.y *= Q_SCALE; }
                    vv.x = tf32f(vv.x); vv.y = tf32f(vv.y);
                    *(float2*)(dst + (((size_t)(bb * H_SZ + hh) * T_SZ + t) * D_SZ + d)) = vv;
                } else if (MODE == 1) {
                    float2 bz = *(const float2*)(bias + col);
                    float2 rr = *(const float2*)(res + (size_t)m * Ntot + col);
                    vv.x += bz.x + rr.x; vv.y += bz.y + rr.y;
                    *(float2*)(out + (size_t)m * Ntot + col) = vv;
                } else {
                    float2 bz = *(const float2*)(bias + col);
                    vv.x = tf32f(fmaxf(vv.x + bz.x, 0.0f));
                    vv.y = tf32f(fmaxf(vv.y + bz.y, 0.0f));
                    *(float2*)(out + (size_t)m * Ntot + col) = vv;
                }
            }
        }
    }
}

// ---------------------------------------------------------------------------
// Small-tile GEMM for the N=256 layers (proj, ff2): BM=64, BN=128, BK=32,
// 2-stage cp.async, 3 blocks/SM (~80 regs). Doubles block count (512) so the
// grid fills 148 SMs with >1 full wave. Epilogue: out = acc + bias + res.
// Per-output accumulation order identical to the BM=128 kernel.
// ---------------------------------------------------------------------------
#define GA_TILE_W (64 * PAD2)                        // 2304 words (A tile)
#define GB_TILE_W (128 * PAD2)                       // 4608 words (B tile)
#define GEMM64_SMEM ((2 * GA_TILE_W + 2 * GB_TILE_W) * 4)   // 55296 bytes

__global__ __launch_bounds__(256, 3)
void gemm_tc64(const float* __restrict__ A, const float* __restrict__ Bw,
               const float* __restrict__ bias, const float* __restrict__ res,
               float* __restrict__ out, int Ntot, int K) {
    extern __shared__ __align__(16) uint32_t dynsm[];

    const int tid  = threadIdx.x;
    const int wid  = tid >> 5;
    const int lane = tid & 31;
    const int g    = lane >> 2;
    const int tg   = lane & 3;
    const int wm   = wid & 1;       // 0..1 -> 32-row slab
    const int wn   = wid >> 1;      // 0..3 -> 32-col slab
    const int m0   = blockIdx.y * 64;
    const int n0   = blockIdx.x * 128;

    // A loader: 64 rows x 8 c4-chunks = 512; 2 per thread (contiguous 32B)
    const int laA_row = tid >> 2;              // 0..63
    const int laA_c4  = (tid & 3) << 3;        // 0,8,16,24 (word offset; 2 chunks)
    // B loader: 128 rows x 8 c4-chunks = 1024; 4 per thread (contiguous 64B)
    const int laB_row = tid >> 1;              // 0..127
    const int laB_c4  = (tid & 1) << 4;        // 0 or 16 (word offset; 4 chunks)

    const uint32_t sbase = smem_u32(dynsm);
    const uint32_t sB = sbase + 2 * GA_TILE_W * 4;

    float acc[2][4][4];
    #pragma unroll
    for (int i = 0; i < 2; i++)
        #pragma unroll
        for (int j = 0; j < 4; j++)
            #pragma unroll
            for (int r = 0; r < 4; r++) acc[i][j][r] = 0.0f;

    const int nchunks = K >> 5;

    {
        #pragma unroll
        for (int e = 0; e < 2; e++)
            CP_ASYNC16(sbase + (laA_row * PAD2 + laA_c4 + e * 4) * 4,
                       A + (size_t)(m0 + laA_row) * K + laA_c4 + e * 4);
        #pragma unroll
        for (int e = 0; e < 4; e++)
            CP_ASYNC16(sB + (laB_row * PAD2 + laB_c4 + e * 4) * 4,
                       Bw + (size_t)(n0 + laB_row) * K + laB_c4 + e * 4);
        CP_COMMIT();
    }

    for (int c = 0; c < nchunks; c++) {
        CP_WAIT0();
        __syncthreads();
        if (c + 1 < nchunks) {
            const int st2 = (c + 1) & 1;
            const int k0 = (c + 1) << 5;
            #pragma unroll
            for (int e = 0; e < 2; e++)
                CP_ASYNC16(sbase + (st2 * GA_TILE_W + laA_row * PAD2 + laA_c4 + e * 4) * 4,
                           A + (size_t)(m0 + laA_row) * K + k0 + laA_c4 + e * 4);
            #pragma unroll
            for (int e = 0; e < 4; e++)
                CP_ASYNC16(sB + (st2 * GB_TILE_W + laB_row * PAD2 + laB_c4 + e * 4) * 4,
                           Bw + (size_t)(n0 + laB_row) * K + k0 + laB_c4 + e * 4);
            CP_COMMIT();
        }
        const int st = c & 1;
        const uint32_t* As = dynsm + st * GA_TILE_W;
        const uint32_t* Bs = dynsm + 2 * GA_TILE_W + st * GB_TILE_W;

        #pragma unroll
        for (int kk = 0; kk < 32; kk += 8) {
            uint32_t af[2][4], bf[4][2];
            #pragma unroll
            for (int i = 0; i < 2; i++) {
                int r0 = wm * 32 + i * 16 + g;
                af[i][0] = As[r0 * PAD2 + kk + tg];
                af[i][1] = As[(r0 + 8) * PAD2 + kk + tg];
                af[i][2] = As[r0 * PAD2 + kk + tg + 4];
                af[i][3] = As[(r0 + 8) * PAD2 + kk + tg + 4];
            }
            #pragma unroll
            for (int j = 0; j < 4; j++) {
                int n = wn * 32 + j * 8 + g;
                bf[j][0] = Bs[n * PAD2 + kk + tg];
                bf[j][1] = Bs[n * PAD2 + kk + tg + 4];
            }
            #pragma unroll
            for (int i = 0; i < 2; i++)
                #pragma unroll
                for (int j = 0; j < 4; j++)
                    mma_tf32(acc[i][j], af[i], bf[j]);
        }
    }

    #pragma unroll
    for (int i = 0; i < 2; i++) {
        #pragma unroll
        for (int half = 0; half < 2; half++) {
            int m = m0 + wm * 32 + i * 16 + g + half * 8;
            #pragma unroll
            for (int j = 0; j < 4; j++) {
                int col = n0 + wn * 32 + j * 8 + tg * 2;
                float2 vv = make_float2(acc[i][j][half * 2], acc[i][j][half * 2 + 1]);
                float2 bz = *(const float2*)(bias + col);
                float2 rr = *(const float2*)(res + (size_t)m * Ntot + col);
                vv.x += bz.x + rr.x; vv.y += bz.y + rr.y;
                *(float2*)(out + (size_t)m * Ntot + col) = vv;
            }
        }
    }
}

// ---------------------------------------------------------------------------
// Tensor-core flash attention (round-14 known-good): MAX-FREE base-2 softmax,
// monolithic 64-key tiles, deferred l-reduction, P-in-registers raw-bit tf32,
// 3-stage cp.async, 3 blocks/SM.
// ---------------------------------------------------------------------------
#define KS_STR 36
#define A_TILE_W (64 * KS_STR)
#define ATTN_SMEM (3 * A_TILE_W * 2 * 4)             // 55296 bytes

__global__ __launch_bounds__(128, 3)
void attn_mma(const float* __restrict__ q, const float* __restrict__ k,
              const float* __restrict__ v, float* __restrict__ out) {
    extern __shared__ __align__(16) uint32_t asm_[];

    const int tid  = threadIdx.x;
    const int wq_  = tid >> 5;
    const int lane = tid & 31;
    const int g    = lane >> 2;
    const int tg   = lane & 3;
    const int qt   = (int)gridDim.x - 1 - (int)blockIdx.x;  // diagonal-first
    const int bh   = blockIdx.y;
    const int q0   = qt * 128;
    const int qw   = q0 + wq_ * 32;

    const float* qbase = q + ((size_t)bh << 10) * D_SZ;
    const float* kbase = k + ((size_t)bh << 10) * D_SZ;
    const float* vbase = v + ((size_t)bh << 10) * D_SZ;

    const int ld_row = tid >> 3;
    const int ld_c4  = (tid & 7) << 2;
    const uint32_t sbase = smem_u32(asm_);

    const int nkt = 2 * qt + 2;

    // prologue: issue tiles 0 and 1
    #pragma unroll
    for (int p = 0; p < 2; p++) {
        const uint32_t so = p * A_TILE_W * 4;
        const float* kb = kbase + (size_t)(p * 64) * 32;
        const float* vb_ = vbase + (size_t)(p * 64) * 32;
        #pragma unroll
        for (int e = 0; e < 4; e++) {
            int row = ld_row + e * 16;
            CP_ASYNC16(sbase + so + (row * KS_STR + ld_c4) * 4, kb + row * 32 + ld_c4);
            CP_ASYNC16(sbase + 3 * A_TILE_W * 4 + so + (row * KS_STR + ld_c4) * 4,
                       vb_ + row * 32 + ld_c4);
        }
        CP_COMMIT();
    }

    // Q fragments (pre-scaled by log2e/16 + pre-rounded by producer)
    uint32_t qa[2][4][4];
    #pragma unroll
    for (int i = 0; i < 2; i++)
        #pragma unroll
        for (int kc = 0; kc < 4; kc++) {
            int r0 = qw + 16 * i + g;
            int c0 = kc * 8 + tg;
            qa[i][kc][0] = __float_as_uint(qbase[(size_t)r0 * 32 + c0]);
            qa[i][kc][1] = __float_as_uint(qbase[(size_t)(r0 + 8) * 32 + c0]);
            qa[i][kc][2] = __float_as_uint(qbase[(size_t)r0 * 32 + c0 + 4]);
            qa[i][kc][3] = __float_as_uint(qbase[(size_t)(r0 + 8) * 32 + c0 + 4]);
        }

    float o_[2][4][4];
    #pragma unroll
    for (int i = 0; i < 2; i++)
        #pragma unroll
        for (int j = 0; j < 4; j++)
            #pragma unroll
            for (int r = 0; r < 4; r++) o_[i][j][r] = 0.0f;
    float l_[2][2] = {{0.f, 0.f}, {0.f, 0.f}};   // per-thread partial sums

    for (int ktile = 0; ktile < nkt; ktile++) {
        if (ktile + 1 < nkt) { CP_WAIT1(); } else { CP_WAIT0(); }
        __syncthreads();
        if (ktile + 2 < nkt) {
            const int st2 = (ktile + 2) % 3;
            const uint32_t so = st2 * A_TILE_W * 4;
            const float* kb = kbase + (size_t)((ktile + 2) * 64) * 32;
            const float* vb_ = vbase + (size_t)((ktile + 2) * 64) * 32;
            #pragma unroll
            for (int e = 0; e < 4; e++) {
                int row = ld_row + e * 16;
                CP_ASYNC16(sbase + so + (row * KS_STR + ld_c4) * 4, kb + row * 32 + ld_c4);
                CP_ASYNC16(sbase + 3 * A_TILE_W * 4 + so + (row * KS_STR + ld_c4) * 4,
                           vb_ + row * 32 + ld_c4);
            }
            CP_COMMIT();
        }

        const int s0 = ktile * 64;
        const int st = ktile % 3;
        const uint32_t* Ks = asm_ + st * A_TILE_W;
        const uint32_t* Vs = asm_ + 3 * A_TILE_W + st * A_TILE_W;

        if (s0 <= qw + 31) {
            float S[2][8][4];
            #pragma unroll
            for (int i = 0; i < 2; i++)
                #pragma unroll
                for (int j = 0; j < 8; j++)
                    #pragma unroll
                    for (int r = 0; r < 4; r++) S[i][j][r] = 0.0f;

            // S = Q K^T  (log2 domain)
            #pragma unroll
            for (int kc = 0; kc < 4; kc++) {
                uint32_t bf[8][2];
                #pragma unroll
                for (int j = 0; j < 8; j++) {
                    bf[j][0] = Ks[(j * 8 + g) * KS_STR + kc * 8 + tg];
                    bf[j][1] = Ks[(j * 8 + g) * KS_STR + kc * 8 + tg + 4];
                }
                #pragma unroll
                for (int i = 0; i < 2; i++)
                    #pragma unroll
                    for (int j = 0; j < 8; j++)
                        mma_tf32(S[i][j], qa[i][kc], bf[j]);
            }
            // causal mask
            if (s0 + 63 > qw) {
                #pragma unroll
                for (int i = 0; i < 2; i++)
                    #pragma unroll
                    for (int h = 0; h < 2; h++) {
                        int qrow = qw + 16 * i + g + 8 * h;
                        #pragma unroll
                        for (int j = 0; j < 8; j++) {
                            int sc = s0 + j * 8 + 2 * tg;
                            if (sc > qrow)     S[i][j][2 * h]     = -1e30f;
                            if (sc + 1 > qrow) S[i][j][2 * h + 1] = -1e30f;
                        }
                    }
            }
            // max-free softmax: p = 2^S; accumulate private partial sums
            #pragma unroll
            for (int i = 0; i < 2; i++)
                #pragma unroll
                for (int h = 0; h < 2; h++) {
                    float sum = 0.0f;
                    #pragma unroll
                    for (int j = 0; j < 8; j++) {
                        float p0 = ex2f(S[i][j][2 * h]);
                        float p1 = ex2f(S[i][j][2 * h + 1]);
                        S[i][j][2 * h] = p0; S[i][j][2 * h + 1] = p1;
                        sum += p0 + p1;
                    }
                    l_[i][h] += sum;
                }

            // O += P V  (P regs passed RAW as tf32 operands; permuted k-dim)
            #pragma unroll
            for (int kf = 0; kf < 8; kf++) {
                uint32_t vb[4][2];
                #pragma unroll
                for (int jn = 0; jn < 4; jn++) {
                    vb[jn][0] = Vs[(kf * 8 + 2 * tg)     * KS_STR + jn * 8 + g];
                    vb[jn][1] = Vs[(kf * 8 + 2 * tg + 1) * KS_STR + jn * 8 + g];
                }
                #pragma unroll
                for (int i = 0; i < 2; i++) {
                    uint32_t pa[4];
                    pa[0] = __float_as_uint(S[i][kf][0]);
                    pa[1] = __float_as_uint(S[i][kf][2]);
                    pa[2] = __float_as_uint(S[i][kf][1]);
                    pa[3] = __float_as_uint(S[i][kf][3]);
                    #pragma unroll
                    for (int jn = 0; jn < 4; jn++)
                        mma_tf32(o_[i][jn], pa, vb[jn]);
                }
            }
        }
    }

    // epilogue: finish l reduction, then write out
    const int bb = bh >> 3, hh = bh & 7;
    #pragma unroll
    for (int i = 0; i < 2; i++)
        #pragma unroll
        for (int h = 0; h < 2; h++) {
            float lv = l_[i][h];
            lv += __shfl_xor_sync(0xFFFFFFFFu, lv, 1);
            lv += __shfl_xor_sync(0xFFFFFFFFu, lv, 2);
            int trow = q0 + wq_ * 32 + 16 * i + g + 8 * h;
            float nv = 1.0f / lv;
            #pragma unroll
            for (int jn = 0; jn < 4; jn++) {
                float2 ov = make_float2(tf32f(o_[i][jn][2 * h] * nv),
                                        tf32f(o_[i][jn][2 * h + 1] * nv));
                int col = jn * 8 + 2 * tg;
                *(float2*)(out + ((size_t)((bb << 10) + trow) * C_SZ + hh * 32 + col)) = ov;
            }
        }
}

// ---------------------------------------------------------------------------
extern "C" void kernel_launch(void* const* d_in, const int* in_sizes, int n_in,
                              void* d_out, int out_size) {
    (void)in_sizes; (void)n_in; (void)out_size;
    const float* x      = (const float*)d_in[0];
    const float* wq     = (const float*)d_in[1];
    const float* wk     = (const float*)d_in[2];
    const float* wv     = (const float*)d_in[3];
    const float* w_proj = (const float*)d_in[4];
    const float* b_proj = (const float*)d_in[5];
    const float* w1     = (const float*)d_in[6];
    const float* b1     = (const float*)d_in[7];
    const float* w2     = (const float*)d_in[8];
    const float* b2     = (const float*)d_in[9];
    const float* ln1_g  = (const float*)d_in[10];
    const float* ln1_b  = (const float*)d_in[11];
    const float* ln2_g  = (const float*)d_in[12];
    const float* ln2_b  = (const float*)d_in[13];
    float* out = (float*)d_out;

    float *h, *qb, *kb, *vb, *att, *x1, *h2, *f1;
    float *wqkvT, *wprojT, *w1T, *w2T;
    cudaGetSymbolAddress((void**)&h,   g_h);
    cudaGetSymbolAddress((void**)&qb,  g_q);
    cudaGetSymbolAddress((void**)&kb,  g_k);
    cudaGetSymbolAddress((void**)&vb,  g_v);
    cudaGetSymbolAddress((void**)&att, g_att);
    cudaGetSymbolAddress((void**)&x1,  g_x1);
    cudaGetSymbolAddress((void**)&h2,  g_h2);
    cudaGetSymbolAddress((void**)&f1,  g_f1);
    cudaGetSymbolAddress((void**)&wqkvT,  g_wqkvT);
    cudaGetSymbolAddress((void**)&wprojT, g_wprojT);
    cudaGetSymbolAddress((void**)&w1T,    g_w1T);
    cudaGetSymbolAddress((void**)&w2T,    g_w2T);

    cudaFuncSetAttribute(attn_mma, cudaFuncAttributeMaxDynamicSharedMemorySize, ATTN_SMEM);
    cudaFuncSetAttribute(gemm_tc<0>, cudaFuncAttributeMaxDynamicSharedMemorySize, GEMM_SMEM);
    cudaFuncSetAttribute(gemm_tc<2>, cudaFuncAttributeMaxDynamicSharedMemorySize, GEMM_SMEM);
    cudaFuncSetAttribute(gemm_tc64, cudaFuncAttributeMaxDynamicSharedMemorySize, GEMM64_SMEM);

    // 0+1. Weight prep + LN1 (independent; fused into one launch)
    prep_and_ln1<<<768 + M_ROWS / 8, 256>>>(wq, wk, wv, w_proj, w1, w2,
                                            wqkvT, wprojT, w1T, w2T,
                                            x, ln1_g, ln1_b, h);
    // 2. Fused QKV projection (N=768) -> scatter to [B,H,T,D]
    gemm_tc<0><<<dim3(768 / 128, M_ROWS / 128), 256, GEMM_SMEM>>>(
        h, wqkvT, nullptr, nullptr, qb, kb, vb, 768, C_SZ);
    // 3. Causal flash attention
    attn_mma<<<dim3(T_SZ / 128, B_SZ * H_SZ), 128, ATTN_SMEM>>>(qb, kb, vb, att);
    // 4. Output projection + bias + residual (small-tile GEMM: 512 blocks)
    gemm_tc64<<<dim3(C_SZ / 128, M_ROWS / 64), 256, GEMM64_SMEM>>>(
        att, wprojT, b_proj, x, x1, C_SZ, C_SZ);
    // 5. LN2
    ln_kernel<<<M_ROWS / 8, 256>>>(x1, ln2_g, ln2_b, h2);
    // 6. FF1 + ReLU (N=1024)
    gemm_tc<2><<<dim3(FF_SZ / 128, M_ROWS / 128), 256, GEMM_SMEM>>>(
        h2, w1T, b1, nullptr, f1, nullptr, nullptr, FF_SZ, C_SZ);
    // 7. FF2 + bias + residual -> out (small-tile GEMM, K=1024)
    gemm_tc64<<<dim3(C_SZ / 128, M_ROWS / 64), 256, GEMM64_SMEM>>>(
        f1, w2T, b2, x1, out, C_SZ, FF_SZ);
}

// round 16
// speedup vs baseline: 1.2046x; 1.2046x over previous
#include <cuda_runtime.h>
#include <cstdint>
#include <math.h>

// Problem constants
#define B_SZ   16
#define T_SZ   1024
#define C_SZ   256
#define H_SZ   8
#define D_SZ   32
#define M_ROWS (B_SZ * T_SZ)      // 16384
#define FF_SZ  (4 * C_SZ)         // 1024

// Scratch (allocation-free rule: __device__ globals)
__device__ float g_h  [M_ROWS * C_SZ];
__device__ float g_q  [M_ROWS * C_SZ];   // [B,H,T,D] (scaled log2e/16, tf32, d-PERMUTED)
__device__ float g_k  [M_ROWS * C_SZ];   // tf32, d-PERMUTED
__device__ float g_v  [M_ROWS * C_SZ];   // tf32 (logical d order)
__device__ float g_att[M_ROWS * C_SZ];   // [B,T,C]  tf32-rounded
__device__ float g_x1 [M_ROWS * C_SZ];   // full fp32 (residual path)
__device__ float g_h2 [M_ROWS * C_SZ];   // tf32-rounded
__device__ float g_f1 [M_ROWS * FF_SZ];  // tf32-rounded
// Transposed (K-major) weights, tf32-rounded
__device__ float g_wqkvT[768 * 256];
__device__ float g_wprojT[256 * 256];
__device__ float g_w1T  [1024 * 256];
__device__ float g_w2T  [256 * 1024];

// ---------------------------------------------------------------------------
// mma.sync tf32 helpers
// ---------------------------------------------------------------------------
__device__ __forceinline__ uint32_t f2tf32(float x) {
    uint32_t r;
    asm("cvt.rna.tf32.f32 %0, %1;" : "=r"(r) : "f"(x));
    return r;
}
__device__ __forceinline__ float tf32f(float x) {
    return __uint_as_float(f2tf32(x));
}
__device__ __forceinline__ float ex2f(float x) {
    float r;
    asm("ex2.approx.f32 %0, %1;" : "=f"(r) : "f"(x));
    return r;
}
__device__ __forceinline__ void mma_tf32(float* d, const uint32_t* a, const uint32_t* b) {
    asm volatile(
        "mma.sync.aligned.m16n8k8.row.col.f32.tf32.tf32.f32 "
        "{%0,%1,%2,%3}, {%4,%5,%6,%7}, {%8,%9}, {%0,%1,%2,%3};\n"
        : "+f"(d[0]), "+f"(d[1]), "+f"(d[2]), "+f"(d[3])
        : "r"(a[0]), "r"(a[1]), "r"(a[2]), "r"(a[3]), "r"(b[0]), "r"(b[1]));
}

#define CP_ASYNC16(dst, src) \
    asm volatile("cp.async.ca.shared.global [%0], [%1], 16;" :: "r"(dst), "l"(src))
#define CP_COMMIT() asm volatile("cp.async.commit_group;" ::: "memory")
#define CP_WAIT1()  asm volatile("cp.async.wait_group 1;" ::: "memory")
#define CP_WAIT0()  asm volatile("cp.async.wait_group 0;" ::: "memory")

__device__ __forceinline__ uint32_t smem_u32(const void* p) {
    uint32_t a;
    asm("{ .reg .u64 t; cvta.to.shared.u64 t, %1; cvt.u32.u64 %0, t; }" : "=r"(a) : "l"(p));
    return a;
}

// d-permutation within each 8-group: logical m -> physical p(m)
// pairs (m, m+4) land adjacent: p(m) = m<4 ? 2m : 2(m-4)+1
__device__ __forceinline__ int dperm(int m) {
    return (m < 4) ? (m << 1) : (((m - 4) << 1) | 1);
}

// ---------------------------------------------------------------------------
// Fused prep: blocks [0,768) = weight transposes/pack; [768, 768+2048) = LN1.
// ---------------------------------------------------------------------------
__global__ void prep_and_ln1(const float* __restrict__ wq, const float* __restrict__ wk,
                             const float* __restrict__ wv, const float* __restrict__ w_proj,
                             const float* __restrict__ w1, const float* __restrict__ w2,
                             float* __restrict__ wqkvT, float* __restrict__ wprojT,
                             float* __restrict__ w1T, float* __restrict__ w2T,
                             const float* __restrict__ x, const float* __restrict__ ln_g,
                             const float* __restrict__ ln_b, float* __restrict__ hout) {
    __shared__ float tile[32][33];
    int t = blockIdx.x;
    if (t < 768) {
        int tx = threadIdx.x & 31, ty = threadIdx.x >> 5;   // (32, 8)
        const float* in; float* out; int rows, cols, bx, by;
        if (t < 192) {
            int sel = t / 64, rem = t % 64;
            int h = rem >> 3, cbi = rem & 7;
            const float* w = (sel == 0) ? wq : (sel == 1) ? wk : wv;
            in  = w + h * (C_SZ * D_SZ);
            out = wqkvT + (size_t)(sel * 256 + h * 32) * C_SZ;
            rows = 256; cols = 32; by = cbi * 32; bx = 0;
        } else if (t < 256) {
            int r = t - 192; in = w_proj; out = wprojT; rows = 256; cols = 256;
            bx = (r & 7) * 32; by = (r >> 3) * 32;
        } else if (t < 512) {
            int r = t - 256; in = w1; out = w1T; rows = 256; cols = 1024;
            bx = (r & 31) * 32; by = (r >> 5) * 32;
        } else {
            int r = t - 512; in = w2; out = w2T; rows = 1024; cols = 256;
            bx = (r & 7) * 32; by = (r >> 3) * 32;
        }
        #pragma unroll
        for (int e = 0; e < 4; e++)
            tile[ty + e*8][tx] = in[(size_t)(by + ty + e*8) * cols + bx + tx];
        __syncthreads();
        #pragma unroll
        for (int e = 0; e < 4; e++)
            out[(size_t)(bx + ty + e*8) * rows + by + tx] = tf32f(tile[tx][ty + e*8]);
    } else {
        int warp = threadIdx.x >> 5;
        int lane = threadIdx.x & 31;
        int row  = (t - 768) * 8 + warp;

        const float4* xr = (const float4*)(x + (size_t)row * C_SZ);
        float4 v0 = xr[lane];
        float4 v1 = xr[lane + 32];

        float s  = v0.x + v0.y + v0.z + v0.w + v1.x + v1.y + v1.z + v1.w;
        float ss = v0.x*v0.x + v0.y*v0.y + v0.z*v0.z + v0.w*v0.w
                 + v1.x*v1.x + v1.y*v1.y + v1.z*v1.z + v1.w*v1.w;

        #pragma unroll
        for (int o = 16; o; o >>= 1) {
            s  += __shfl_xor_sync(0xFFFFFFFFu, s,  o);
            ss += __shfl_xor_sync(0xFFFFFFFFu, ss, o);
        }
        float mu  = s * (1.0f / C_SZ);
        float var = ss * (1.0f / C_SZ) - mu * mu;
        float inv = rsqrtf(var + 1e-5f);

        const float4* gr = (const float4*)ln_g;
        const float4* br = (const float4*)ln_b;
        float4 g0 = gr[lane], g1 = gr[lane + 32];
        float4 b0 = br[lane], b1 = br[lane + 32];

        float4 o0, o1;
        o0.x = tf32f((v0.x - mu) * inv * g0.x + b0.x);
        o0.y = tf32f((v0.y - mu) * inv * g0.y + b0.y);
        o0.z = tf32f((v0.z - mu) * inv * g0.z + b0.z);
        o0.w = tf32f((v0.w - mu) * inv * g0.w + b0.w);
        o1.x = tf32f((v1.x - mu) * inv * g1.x + b1.x);
        o1.y = tf32f((v1.y - mu) * inv * g1.y + b1.y);
        o1.z = tf32f((v1.z - mu) * inv * g1.z + b1.z);
        o1.w = tf32f((v1.w - mu) * inv * g1.w + b1.w);

        float4* orow = (float4*)(hout + (size_t)row * C_SZ);
        orow[lane]      = o0;
        orow[lane + 32] = o1;
    }
}

// ---------------------------------------------------------------------------
// LayerNorm (standalone, used for LN2)
// ---------------------------------------------------------------------------
__global__ void ln_kernel(const float* __restrict__ x,
                          const float* __restrict__ g,
                          const float* __restrict__ b,
                          float* __restrict__ out) {
    int warp = threadIdx.x >> 5;
    int lane = threadIdx.x & 31;
    int row  = blockIdx.x * 8 + warp;

    const float4* xr = (const float4*)(x + (size_t)row * C_SZ);
    float4 v0 = xr[lane];
    float4 v1 = xr[lane + 32];

    float s  = v0.x + v0.y + v0.z + v0.w + v1.x + v1.y + v1.z + v1.w;
    float ss = v0.x*v0.x + v0.y*v0.y + v0.z*v0.z + v0.w*v0.w
             + v1.x*v1.x + v1.y*v1.y + v1.z*v1.z + v1.w*v1.w;

    #pragma unroll
    for (int o = 16; o; o >>= 1) {
        s  += __shfl_xor_sync(0xFFFFFFFFu, s,  o);
        ss += __shfl_xor_sync(0xFFFFFFFFu, ss, o);
    }
    float mu  = s * (1.0f / C_SZ);
    float var = ss * (1.0f / C_SZ) - mu * mu;
    float inv = rsqrtf(var + 1e-5f);

    const float4* gr = (const float4*)g;
    const float4* br = (const float4*)b;
    float4 g0 = gr[lane], g1 = gr[lane + 32];
    float4 b0 = br[lane], b1 = br[lane + 32];

    float4 o0, o1;
    o0.x = tf32f((v0.x - mu) * inv * g0.x + b0.x);
    o0.y = tf32f((v0.y - mu) * inv * g0.y + b0.y);
    o0.z = tf32f((v0.z - mu) * inv * g0.z + b0.z);
    o0.w = tf32f((v0.w - mu) * inv * g0.w + b0.w);
    o1.x = tf32f((v1.x - mu) * inv * g1.x + b1.x);
    o1.y = tf32f((v1.y - mu) * inv * g1.y + b1.y);
    o1.z = tf32f((v1.z - mu) * inv * g1.z + b1.z);
    o1.w = tf32f((v1.w - mu) * inv * g1.w + b1.w);

    float4* orow = (float4*)(out + (size_t)row * C_SZ);
    orow[lane]      = o0;
    orow[lane + 32] = o1;
}

// ---------------------------------------------------------------------------
// tf32 HMMA GEMM, BM=128 BN=128 BK=32, 2-stage cp.async, 2 blocks/SM.
// (round-14 proven configuration)
// MODE 0: scatter to q/k/v; q,k written d-PERMUTED (attention layout).
// ---------------------------------------------------------------------------
#define PAD2 36
#define G2_TILE_W (128 * PAD2)                      // 4608 words per operand tile
#define GEMM_SMEM (2 * G2_TILE_W * 2 * 4)           // 73728 bytes
#define Q_SCALE 0.09016844f                         // (1/16) * log2(e)

template <int MODE>
__global__ __launch_bounds__(256, 2)
void gemm_tc(const float* __restrict__ A, const float* __restrict__ Bw,
             const float* __restrict__ bias, const float* __restrict__ res,
             float* __restrict__ out, float* __restrict__ out2, float* __restrict__ out3,
             int Ntot, int K) {
    extern __shared__ __align__(16) uint32_t dynsm[];

    const int tid  = threadIdx.x;
    const int wid  = tid >> 5;
    const int lane = tid & 31;
    const int g    = lane >> 2;
    const int tg   = lane & 3;
    const int wm   = wid & 1;
    const int wn   = wid >> 1;
    const int m0   = blockIdx.y * 128;
    const int n0   = blockIdx.x * 128;

    const int ld_row = tid >> 3;
    const int ld_c4  = (tid & 7) << 2;
    const uint32_t sbase = smem_u32(dynsm);

    float acc[4][4][4];
    #pragma unroll
    for (int i = 0; i < 4; i++)
        #pragma unroll
        for (int j = 0; j < 4; j++)
            #pragma unroll
            for (int r = 0; r < 4; r++) acc[i][j][r] = 0.0f;

    const int nchunks = K >> 5;

    {
        #pragma unroll
        for (int e = 0; e < 4; e++) {
            int row = ld_row + e * 32;
            CP_ASYNC16(sbase + (row * PAD2 + ld_c4) * 4,
                       A + (size_t)(m0 + row) * K + ld_c4);
            CP_ASYNC16(sbase + (2 * G2_TILE_W + row * PAD2 + ld_c4) * 4,
                       Bw + (size_t)(n0 + row) * K + ld_c4);
        }
        CP_COMMIT();
    }

    for (int c = 0; c < nchunks; c++) {
        CP_WAIT0();
        __syncthreads();
        if (c + 1 < nchunks) {
            const int st2 = (c + 1) & 1;
            const int k0 = (c + 1) << 5;
            #pragma unroll
            for (int e = 0; e < 4; e++) {
                int row = ld_row + e * 32;
                CP_ASYNC16(sbase + (st2 * G2_TILE_W + row * PAD2 + ld_c4) * 4,
                           A + (size_t)(m0 + row) * K + k0 + ld_c4);
                CP_ASYNC16(sbase + ((2 + st2) * G2_TILE_W + row * PAD2 + ld_c4) * 4,
                           Bw + (size_t)(n0 + row) * K + k0 + ld_c4);
            }
            CP_COMMIT();
        }
        const int st = c & 1;
        const uint32_t* As = dynsm + st * G2_TILE_W;
        const uint32_t* Bs = dynsm + (2 + st) * G2_TILE_W;

        #pragma unroll
        for (int kk = 0; kk < 32; kk += 8) {
            uint32_t af[4][4], bf[4][2];
            #pragma unroll
            for (int i = 0; i < 4; i++) {
                int r0 = wm * 64 + i * 16 + g;
                af[i][0] = As[r0 * PAD2 + kk + tg];
                af[i][1] = As[(r0 + 8) * PAD2 + kk + tg];
                af[i][2] = As[r0 * PAD2 + kk + tg + 4];
                af[i][3] = As[(r0 + 8) * PAD2 + kk + tg + 4];
            }
            #pragma unroll
            for (int j = 0; j < 4; j++) {
                int n = wn * 32 + j * 8 + g;
                bf[j][0] = Bs[n * PAD2 + kk + tg];
                bf[j][1] = Bs[n * PAD2 + kk + tg + 4];
            }
            #pragma unroll
            for (int i = 0; i < 4; i++)
                #pragma unroll
                for (int j = 0; j < 4; j++)
                    mma_tf32(acc[i][j], af[i], bf[j]);
        }
    }

    #pragma unroll
    for (int i = 0; i < 4; i++) {
        #pragma unroll
        for (int half = 0; half < 2; half++) {
            int m  = m0 + wm * 64 + i * 16 + g + half * 8;
            int bb = m >> 10, t = m & 1023;
            #pragma unroll
            for (int j = 0; j < 4; j++) {
                int col = n0 + wn * 32 + j * 8 + tg * 2;
                float2 vv = make_float2(acc[i][j][half * 2], acc[i][j][half * 2 + 1]);
                if (MODE == 0) {
                    int tsel = col >> 8;
                    int c2 = col & 255;
                    int hh = c2 >> 5, d = c2 & 31;
                    float* dst = (tsel == 0) ? out : (tsel == 1) ? out2 : out3;
                    if (tsel == 0) { vv.x *= Q_SCALE; vv.y *= Q_SCALE; }
                    vv.x = tf32f(vv.x); vv.y = tf32f(vv.y);
                    size_t base = ((size_t)(bb * H_SZ + hh) * T_SZ + t) * D_SZ;
                    if (tsel == 2) {
                        *(float2*)(dst + base + d) = vv;       // V: logical order
                    } else {
                        // q/k: permute d within 8-group (pairs (m,m+4) adjacent)
                        int grp = d & ~7;
                        int mlo = d & 7;                        // even
                        dst[base + grp + dperm(mlo)]     = vv.x;
                        dst[base + grp + dperm(mlo + 1)] = vv.y;
                    }
                } else if (MODE == 1) {
                    float2 bz = *(const float2*)(bias + col);
                    float2 rr = *(const float2*)(res + (size_t)m * Ntot + col);
                    vv.x += bz.x + rr.x; vv.y += bz.y + rr.y;
                    *(float2*)(out + (size_t)m * Ntot + col) = vv;
                } else {
                    float2 bz = *(const float2*)(bias + col);
                    vv.x = tf32f(fmaxf(vv.x + bz.x, 0.0f));
                    vv.y = tf32f(fmaxf(vv.y + bz.y, 0.0f));
                    *(float2*)(out + (size_t)m * Ntot + col) = vv;
                }
            }
        }
    }
}

// ---------------------------------------------------------------------------
// Tensor-core flash attention (round-14 structure + paired-K LDS.64):
// MAX-FREE base-2 softmax, monolithic 64-key tiles, deferred l-reduction,
// P-in-registers raw-bit tf32, 3-stage cp.async, 3 blocks/SM.
// Q and K are d-PERMUTED by the producer so frag pairs (tg, tg+4) are
// physically adjacent: K B-frags load as one 64-bit LDS (stride 40,
// conflict-free for paired access); Q frags load as float2.
// V stays logical order, stride 36 (unchanged conflict-free pattern).
// ---------------------------------------------------------------------------
#define KSTR_K 40
#define KSTR_V 36
#define KT_W (64 * KSTR_K)                           // 2560 words
#define VT_W (64 * KSTR_V)                           // 2304 words
#define ATTN_SMEM ((3 * KT_W + 3 * VT_W) * 4)        // 58368 bytes

__global__ __launch_bounds__(128, 3)
void attn_mma(const float* __restrict__ q, const float* __restrict__ k,
              const float* __restrict__ v, float* __restrict__ out) {
    extern __shared__ __align__(16) uint32_t asm_[];

    const int tid  = threadIdx.x;
    const int wq_  = tid >> 5;
    const int lane = tid & 31;
    const int g    = lane >> 2;
    const int tg   = lane & 3;
    const int qt   = (int)gridDim.x - 1 - (int)blockIdx.x;  // diagonal-first
    const int bh   = blockIdx.y;
    const int q0   = qt * 128;
    const int qw   = q0 + wq_ * 32;

    const float* qbase = q + ((size_t)bh << 10) * D_SZ;
    const float* kbase = k + ((size_t)bh << 10) * D_SZ;
    const float* vbase = v + ((size_t)bh << 10) * D_SZ;

    const int ld_row = tid >> 3;
    const int ld_c4  = (tid & 7) << 2;
    const uint32_t sbase = smem_u32(asm_);
    const uint32_t vbase_sm = sbase + 3 * KT_W * 4;

    const int nkt = 2 * qt + 2;

    // prologue: issue tiles 0 and 1
    #pragma unroll
    for (int p = 0; p < 2; p++) {
        const float* kb = kbase + (size_t)(p * 64) * 32;
        const float* vb_ = vbase + (size_t)(p * 64) * 32;
        #pragma unroll
        for (int e = 0; e < 4; e++) {
            int row = ld_row + e * 16;
            CP_ASYNC16(sbase + (p * KT_W + row * KSTR_K + ld_c4) * 4, kb + row * 32 + ld_c4);
            CP_ASYNC16(vbase_sm + (p * VT_W + row * KSTR_V + ld_c4) * 4, vb_ + row * 32 + ld_c4);
        }
        CP_COMMIT();
    }

    // Q fragments: producer stored pairs (tg, tg+4) adjacent -> float2 loads
    uint32_t qa[2][4][4];
    #pragma unroll
    for (int i = 0; i < 2; i++)
        #pragma unroll
        for (int kc = 0; kc < 4; kc++) {
            int r0 = qw + 16 * i + g;
            int c0 = kc * 8 + 2 * tg;
            float2 q0p = *(const float2*)(qbase + (size_t)r0 * 32 + c0);
            float2 q1p = *(const float2*)(qbase + (size_t)(r0 + 8) * 32 + c0);
            qa[i][kc][0] = __float_as_uint(q0p.x);   // logical tg
            qa[i][kc][2] = __float_as_uint(q0p.y);   // logical tg+4
            qa[i][kc][1] = __float_as_uint(q1p.x);
            qa[i][kc][3] = __float_as_uint(q1p.y);
        }

    float o_[2][4][4];
    #pragma unroll
    for (int i = 0; i < 2; i++)
        #pragma unroll
        for (int j = 0; j < 4; j++)
            #pragma unroll
            for (int r = 0; r < 4; r++) o_[i][j][r] = 0.0f;
    float l_[2][2] = {{0.f, 0.f}, {0.f, 0.f}};   // per-thread partial sums

    for (int ktile = 0; ktile < nkt; ktile++) {
        if (ktile + 1 < nkt) { CP_WAIT1(); } else { CP_WAIT0(); }
        __syncthreads();
        if (ktile + 2 < nkt) {
            const int st2 = (ktile + 2) % 3;
            const float* kb = kbase + (size_t)((ktile + 2) * 64) * 32;
            const float* vb_ = vbase + (size_t)((ktile + 2) * 64) * 32;
            #pragma unroll
            for (int e = 0; e < 4; e++) {
                int row = ld_row + e * 16;
                CP_ASYNC16(sbase + (st2 * KT_W + row * KSTR_K + ld_c4) * 4,
                           kb + row * 32 + ld_c4);
                CP_ASYNC16(vbase_sm + (st2 * VT_W + row * KSTR_V + ld_c4) * 4,
                           vb_ + row * 32 + ld_c4);
            }
            CP_COMMIT();
        }

        const int s0 = ktile * 64;
        const int st = ktile % 3;
        const uint32_t* Ks = asm_ + st * KT_W;
        const uint32_t* Vs = asm_ + 3 * KT_W + st * VT_W;

        if (s0 <= qw + 31) {
            float S[2][8][4];
            #pragma unroll
            for (int i = 0; i < 2; i++)
                #pragma unroll
                for (int j = 0; j < 8; j++)
                    #pragma unroll
                    for (int r = 0; r < 4; r++) S[i][j][r] = 0.0f;

            // S = Q K^T  (log2 domain); paired 64-bit K frag loads
            #pragma unroll
            for (int kc = 0; kc < 4; kc++) {
                uint32_t bf[8][2];
                #pragma unroll
                for (int j = 0; j < 8; j++) {
                    uint2 kp = *(const uint2*)&Ks[(j * 8 + g) * KSTR_K + kc * 8 + 2 * tg];
                    bf[j][0] = kp.x;   // logical tg
                    bf[j][1] = kp.y;   // logical tg+4
                }
                #pragma unroll
                for (int i = 0; i < 2; i++)
                    #pragma unroll
                    for (int j = 0; j < 8; j++)
                        mma_tf32(S[i][j], qa[i][kc], bf[j]);
            }
            // causal mask
            if (s0 + 63 > qw) {
                #pragma unroll
                for (int i = 0; i < 2; i++)
                    #pragma unroll
                    for (int h = 0; h < 2; h++) {
                        int qrow = qw + 16 * i + g + 8 * h;
                        #pragma unroll
                        for (int j = 0; j < 8; j++) {
                            int sc = s0 + j * 8 + 2 * tg;
                            if (sc > qrow)     S[i][j][2 * h]     = -1e30f;
                            if (sc + 1 > qrow) S[i][j][2 * h + 1] = -1e30f;
                        }
                    }
            }
            // max-free softmax: p = 2^S; accumulate private partial sums
            #pragma unroll
            for (int i = 0; i < 2; i++)
                #pragma unroll
                for (int h = 0; h < 2; h++) {
                    float sum = 0.0f;
                    #pragma unroll
                    for (int j = 0; j < 8; j++) {
                        float p0 = ex2f(S[i][j][2 * h]);
                        float p1 = ex2f(S[i][j][2 * h + 1]);
                        S[i][j][2 * h] = p0; S[i][j][2 * h + 1] = p1;
                        sum += p0 + p1;
                    }
                    l_[i][h] += sum;
                }

            // O += P V  (P regs passed RAW as tf32 operands; permuted k-dim)
            #pragma unroll
            for (int kf = 0; kf < 8; kf++) {
                uint32_t vb[4][2];
                #pragma unroll
                for (int jn = 0; jn < 4; jn++) {
                    vb[jn][0] = Vs[(kf * 8 + 2 * tg)     * KSTR_V + jn * 8 + g];
                    vb[jn][1] = Vs[(kf * 8 + 2 * tg + 1) * KSTR_V + jn * 8 + g];
                }
                #pragma unroll
                for (int i = 0; i < 2; i++) {
                    uint32_t pa[4];
                    pa[0] = __float_as_uint(S[i][kf][0]);
                    pa[1] = __float_as_uint(S[i][kf][2]);
                    pa[2] = __float_as_uint(S[i][kf][1]);
                    pa[3] = __float_as_uint(S[i][kf][3]);
                    #pragma unroll
                    for (int jn = 0; jn < 4; jn++)
                        mma_tf32(o_[i][jn], pa, vb[jn]);
                }
            }
        }
    }

    // epilogue: finish l reduction, then write out
    const int bb = bh >> 3, hh = bh & 7;
    #pragma unroll
    for (int i = 0; i < 2; i++)
        #pragma unroll
        for (int h = 0; h < 2; h++) {
            float lv = l_[i][h];
            lv += __shfl_xor_sync(0xFFFFFFFFu, lv, 1);
            lv += __shfl_xor_sync(0xFFFFFFFFu, lv, 2);
            int trow = q0 + wq_ * 32 + 16 * i + g + 8 * h;
            float nv = 1.0f / lv;
            #pragma unroll
            for (int jn = 0; jn < 4; jn++) {
                float2 ov = make_float2(tf32f(o_[i][jn][2 * h] * nv),
                                        tf32f(o_[i][jn][2 * h + 1] * nv));
                int col = jn * 8 + 2 * tg;
                *(float2*)(out + ((size_t)((bb << 10) + trow) * C_SZ + hh * 32 + col)) = ov;
            }
        }
}

// ---------------------------------------------------------------------------
extern "C" void kernel_launch(void* const* d_in, const int* in_sizes, int n_in,
                              void* d_out, int out_size) {
    (void)in_sizes; (void)n_in; (void)out_size;
    const float* x      = (const float*)d_in[0];
    const float* wq     = (const float*)d_in[1];
    const float* wk     = (const float*)d_in[2];
    const float* wv     = (const float*)d_in[3];
    const float* w_proj = (const float*)d_in[4];
    const float* b_proj = (const float*)d_in[5];
    const float* w1     = (const float*)d_in[6];
    const float* b1     = (const float*)d_in[7];
    const float* w2     = (const float*)d_in[8];
    const float* b2     = (const float*)d_in[9];
    const float* ln1_g  = (const float*)d_in[10];
    const float* ln1_b  = (const float*)d_in[11];
    const float* ln2_g  = (const float*)d_in[12];
    const float* ln2_b  = (const float*)d_in[13];
    float* out = (float*)d_out;

    float *h, *qb, *kb, *vb, *att, *x1, *h2, *f1;
    float *wqkvT, *wprojT, *w1T, *w2T;
    cudaGetSymbolAddress((void**)&h,   g_h);
    cudaGetSymbolAddress((void**)&qb,  g_q);
    cudaGetSymbolAddress((void**)&kb,  g_k);
    cudaGetSymbolAddress((void**)&vb,  g_v);
    cudaGetSymbolAddress((void**)&att, g_att);
    cudaGetSymbolAddress((void**)&x1,  g_x1);
    cudaGetSymbolAddress((void**)&h2,  g_h2);
    cudaGetSymbolAddress((void**)&f1,  g_f1);
    cudaGetSymbolAddress((void**)&wqkvT,  g_wqkvT);
    cudaGetSymbolAddress((void**)&wprojT, g_wprojT);
    cudaGetSymbolAddress((void**)&w1T,    g_w1T);
    cudaGetSymbolAddress((void**)&w2T,    g_w2T);

    cudaFuncSetAttribute(attn_mma, cudaFuncAttributeMaxDynamicSharedMemorySize, ATTN_SMEM);
    cudaFuncSetAttribute(gemm_tc<0>, cudaFuncAttributeMaxDynamicSharedMemorySize, GEMM_SMEM);
    cudaFuncSetAttribute(gemm_tc<1>, cudaFuncAttributeMaxDynamicSharedMemorySize, GEMM_SMEM);
    cudaFuncSetAttribute(gemm_tc<2>, cudaFuncAttributeMaxDynamicSharedMemorySize, GEMM_SMEM);

    // 0+1. Weight prep + LN1 (independent; fused into one launch)
    prep_and_ln1<<<768 + M_ROWS / 8, 256>>>(wq, wk, wv, w_proj, w1, w2,
                                            wqkvT, wprojT, w1T, w2T,
                                            x, ln1_g, ln1_b, h);
    // 2. Fused QKV projection (N=768) -> scatter to [B,H,T,D] (q,k d-permuted)
    gemm_tc<0><<<dim3(768 / 128, M_ROWS / 128), 256, GEMM_SMEM>>>(
        h, wqkvT, nullptr, nullptr, qb, kb, vb, 768, C_SZ);
    // 3. Causal flash attention
    attn_mma<<<dim3(T_SZ / 128, B_SZ * H_SZ), 128, ATTN_SMEM>>>(qb, kb, vb, att);
    // 4. Output projection + bias + residual
    gemm_tc<1><<<dim3(C_SZ / 128, M_ROWS / 128), 256, GEMM_SMEM>>>(
        att, wprojT, b_proj, x, x1, nullptr, nullptr, C_SZ, C_SZ);
    // 5. LN2
    ln_kernel<<<M_ROWS / 8, 256>>>(x1, ln2_g, ln2_b, h2);
    // 6. FF1 + ReLU (N=1024)
    gemm_tc<2><<<dim3(FF_SZ / 128, M_ROWS / 128), 256, GEMM_SMEM>>>(
        h2, w1T, b1, nullptr, f1, nullptr, nullptr, FF_SZ, C_SZ);
    // 7. FF2 + bias + residual -> out (K=1024)
    gemm_tc<1><<<dim3(C_SZ / 128, M_ROWS / 128), 256, GEMM_SMEM>>>(
        f1, w2T, b2, x1, out, nullptr, nullptr, C_SZ, FF_SZ);
}